// round 1
// baseline (speedup 1.0000x reference)
#include <cuda_runtime.h>
#include <math.h>

// Shapes (fixed): B=1, MSA=64, L=256, D=512, H=8, DH=64, HM = H*MSA = 512
#define HM_ 512
#define L_ 256
#define DH_ 64

// Scratch in device globals (allocation-free rule).
// Layouts:
//   g_q/g_k/g_v/g_z : [hm=512][i=256][d=64]   (hm = h*64 + msa)
//   g_S             : [hm=512][i=256][j=256]  scores -> softmax probs (in place)
__device__ float g_q[HM_ * L_ * DH_];
__device__ float g_k[HM_ * L_ * DH_];
__device__ float g_v[HM_ * L_ * DH_];
__device__ float g_z[HM_ * L_ * DH_];
__device__ float g_S[HM_ * L_ * L_];

// ---------------------------------------------------------------------------
// Kernel 1: QKV projection.  Y = X @ W^T  (TN gemm: both K-major row-major)
// X: [16384, 512], W: [512, 512]. 128x128x8 tiling, 256 thr, 8x8/thread.
// Output written in head-split layout directly.
// blockIdx.z selects {Wq->g_q, Wk->g_k, Wv->g_v}.
// ---------------------------------------------------------------------------
__global__ __launch_bounds__(256) void proj_kernel(
    const float* __restrict__ X,
    const float* __restrict__ Wq,
    const float* __restrict__ Wk,
    const float* __restrict__ Wv)
{
    const float* W = (blockIdx.z == 0) ? Wq : (blockIdx.z == 1) ? Wk : Wv;
    float* Y       = (blockIdx.z == 0) ? g_q : (blockIdx.z == 1) ? g_k : g_v;

    __shared__ float As[8][128];
    __shared__ float Bs[8][128];

    int tid = threadIdx.x;
    int tx = tid & 15, ty = tid >> 4;

    int lrow = tid >> 1;          // 0..127
    int lk   = (tid & 1) * 4;     // 0 or 4
    const float* Ap = X + (blockIdx.y * 128 + lrow) * 512 + lk;
    const float* Bp = W + (blockIdx.x * 128 + lrow) * 512 + lk;

    float acc[8][8];
    #pragma unroll
    for (int i = 0; i < 8; i++)
        #pragma unroll
        for (int j = 0; j < 8; j++) acc[i][j] = 0.f;

    for (int k0 = 0; k0 < 512; k0 += 8) {
        float4 av = *(const float4*)(Ap + k0);
        float4 bv = *(const float4*)(Bp + k0);
        As[lk + 0][lrow] = av.x; As[lk + 1][lrow] = av.y;
        As[lk + 2][lrow] = av.z; As[lk + 3][lrow] = av.w;
        Bs[lk + 0][lrow] = bv.x; Bs[lk + 1][lrow] = bv.y;
        Bs[lk + 2][lrow] = bv.z; Bs[lk + 3][lrow] = bv.w;
        __syncthreads();
        #pragma unroll
        for (int kk = 0; kk < 8; kk++) {
            float a[8], b[8];
            *(float4*)&a[0] = *(const float4*)&As[kk][ty * 8];
            *(float4*)&a[4] = *(const float4*)&As[kk][ty * 8 + 4];
            *(float4*)&b[0] = *(const float4*)&Bs[kk][tx * 8];
            *(float4*)&b[4] = *(const float4*)&Bs[kk][tx * 8 + 4];
            #pragma unroll
            for (int i = 0; i < 8; i++)
                #pragma unroll
                for (int j = 0; j < 8; j++)
                    acc[i][j] += a[i] * b[j];
        }
        __syncthreads();
    }

    // Scatter-store into head-split layout: [(h*64+msa)][i][d]
    #pragma unroll
    for (int i = 0; i < 8; i++) {
        int mg  = blockIdx.y * 128 + ty * 8 + i;   // 0..16383
        int msa = mg >> 8;
        int ip  = mg & 255;
        #pragma unroll
        for (int j = 0; j < 8; j++) {
            int n = blockIdx.x * 128 + tx * 8 + j; // 0..511
            int h = n >> 6, d = n & 63;
            Y[(h * 64 + msa) * (L_ * DH_) + ip * DH_ + d] = acc[i][j];
        }
    }
}

// ---------------------------------------------------------------------------
// Kernel 2a: e1 = (q @ k^T) * scale  ->  S
// grid (j_t=4, i_t=4, hm=512), 64x64 tile, K=64, 4x4 per thread.
// ---------------------------------------------------------------------------
__global__ __launch_bounds__(256) void e1_kernel()
{
    int hm = blockIdx.z;
    int it = blockIdx.y * 64;
    int jt = blockIdx.x * 64;

    __shared__ float Qs[64][64];   // [k][i]
    __shared__ float Ks[64][64];   // [k][j]

    int tid = threadIdx.x;
    int r  = tid >> 2;             // 0..63
    int c4 = (tid & 3) * 4;        // 0,4,8,12
    const float* qrow = g_q + hm * (L_ * DH_) + (it + r) * DH_ + c4;
    const float* krow = g_k + hm * (L_ * DH_) + (jt + r) * DH_ + c4;
    #pragma unroll
    for (int s = 0; s < 4; s++) {
        float4 a = *(const float4*)(qrow + s * 16);
        float4 b = *(const float4*)(krow + s * 16);
        int kk = s * 16 + c4;
        Qs[kk + 0][r] = a.x; Qs[kk + 1][r] = a.y; Qs[kk + 2][r] = a.z; Qs[kk + 3][r] = a.w;
        Ks[kk + 0][r] = b.x; Ks[kk + 1][r] = b.y; Ks[kk + 2][r] = b.z; Ks[kk + 3][r] = b.w;
    }
    __syncthreads();

    int tx = tid & 15, ty = tid >> 4;
    float acc[4][4];
    #pragma unroll
    for (int i = 0; i < 4; i++)
        #pragma unroll
        for (int j = 0; j < 4; j++) acc[i][j] = 0.f;

    #pragma unroll 8
    for (int k = 0; k < 64; k++) {
        float4 a = *(const float4*)&Qs[k][ty * 4];
        float4 b = *(const float4*)&Ks[k][tx * 4];
        float av[4] = {a.x, a.y, a.z, a.w};
        float bv[4] = {b.x, b.y, b.z, b.w};
        #pragma unroll
        for (int i = 0; i < 4; i++)
            #pragma unroll
            for (int j = 0; j < 4; j++)
                acc[i][j] += av[i] * bv[j];
    }

    const float scale = 0.125f;  // 1/sqrt(64)
    #pragma unroll
    for (int i = 0; i < 4; i++) {
        float4 o = make_float4(acc[i][0] * scale, acc[i][1] * scale,
                               acc[i][2] * scale, acc[i][3] * scale);
        *(float4*)(g_S + hm * (L_ * L_) + (it + ty * 4 + i) * L_ + jt + tx * 4) = o;
    }
}

// ---------------------------------------------------------------------------
// Kernel 2b: S += scale * (q_i @ aK[i]^T)   blocked by query position i.
// grid (j_t=4, hm_t=8, i=256). 64hm x 64j tile, K=64.
// ---------------------------------------------------------------------------
__global__ __launch_bounds__(256) void e2_kernel(const float* __restrict__ aK)
{
    int i   = blockIdx.z;
    int hm0 = blockIdx.y * 64;
    int jt  = blockIdx.x * 64;

    __shared__ float Qs[64][64];   // [k][hm]
    __shared__ float Bs[64][64];   // [k][j]

    int tid = threadIdx.x;
    int r  = tid >> 2;
    int c4 = (tid & 3) * 4;
    const float* qrow = g_q + (hm0 + r) * (L_ * DH_) + i * DH_ + c4;
    const float* arow = aK + (i * L_ + jt + r) * DH_ + c4;
    #pragma unroll
    for (int s = 0; s < 4; s++) {
        float4 a = *(const float4*)(qrow + s * 16);
        float4 b = *(const float4*)(arow + s * 16);
        int kk = s * 16 + c4;
        Qs[kk + 0][r] = a.x; Qs[kk + 1][r] = a.y; Qs[kk + 2][r] = a.z; Qs[kk + 3][r] = a.w;
        Bs[kk + 0][r] = b.x; Bs[kk + 1][r] = b.y; Bs[kk + 2][r] = b.z; Bs[kk + 3][r] = b.w;
    }
    __syncthreads();

    int tx = tid & 15, ty = tid >> 4;
    float acc[4][4];
    #pragma unroll
    for (int a = 0; a < 4; a++)
        #pragma unroll
        for (int b = 0; b < 4; b++) acc[a][b] = 0.f;

    #pragma unroll 8
    for (int k = 0; k < 64; k++) {
        float4 a = *(const float4*)&Qs[k][ty * 4];
        float4 b = *(const float4*)&Bs[k][tx * 4];
        float av[4] = {a.x, a.y, a.z, a.w};
        float bv[4] = {b.x, b.y, b.z, b.w};
        #pragma unroll
        for (int ii = 0; ii < 4; ii++)
            #pragma unroll
            for (int jj = 0; jj < 4; jj++)
                acc[ii][jj] += av[ii] * bv[jj];
    }

    const float scale = 0.125f;
    #pragma unroll
    for (int ii = 0; ii < 4; ii++) {
        float* Sp = g_S + (hm0 + ty * 4 + ii) * (L_ * L_) + i * L_ + jt + tx * 4;
        float4 o = *(float4*)Sp;
        o.x += acc[ii][0] * scale; o.y += acc[ii][1] * scale;
        o.z += acc[ii][2] * scale; o.w += acc[ii][3] * scale;
        *(float4*)Sp = o;
    }
}

// ---------------------------------------------------------------------------
// Kernel 3: row softmax over j (in place). One block = one row of 256.
// ---------------------------------------------------------------------------
__global__ __launch_bounds__(256) void softmax_kernel()
{
    int row = blockIdx.x;              // 0..131071
    float* p = g_S + row * L_;
    int t = threadIdx.x;
    float v = p[t];

    float m = v;
    #pragma unroll
    for (int o = 16; o > 0; o >>= 1) m = fmaxf(m, __shfl_xor_sync(0xffffffffu, m, o));
    __shared__ float red[8];
    int w = t >> 5, l = t & 31;
    if (l == 0) red[w] = m;
    __syncthreads();
    m = red[0];
    #pragma unroll
    for (int k = 1; k < 8; k++) m = fmaxf(m, red[k]);

    float e = __expf(v - m);
    float s = e;
    #pragma unroll
    for (int o = 16; o > 0; o >>= 1) s += __shfl_xor_sync(0xffffffffu, s, o);
    __syncthreads();
    if (l == 0) red[w] = s;
    __syncthreads();
    s = red[0];
    #pragma unroll
    for (int k = 1; k < 8; k++) s += red[k];

    p[t] = e / s;
}

// ---------------------------------------------------------------------------
// Kernel 4a: z = alpha @ v   (batched over hm). grid (i_t=4, hm=512).
// 64i x 64d tile, loop j in chunks of 64.
// ---------------------------------------------------------------------------
__global__ __launch_bounds__(256) void z1_kernel()
{
    int hm = blockIdx.y;
    int it = blockIdx.x * 64;

    __shared__ float As[64][64];   // [j][i]  (alpha transposed)
    __shared__ float Bs[64][64];   // [j][d]  (v natural)

    int tid = threadIdx.x;
    int r  = tid >> 2;
    int c4 = (tid & 3) * 4;
    int tx = tid & 15, ty = tid >> 4;

    float acc[4][4];
    #pragma unroll
    for (int i = 0; i < 4; i++)
        #pragma unroll
        for (int j = 0; j < 4; j++) acc[i][j] = 0.f;

    for (int jt = 0; jt < L_; jt += 64) {
        const float* arow = g_S + hm * (L_ * L_) + (it + r) * L_ + jt + c4;
        const float* vrow = g_v + hm * (L_ * DH_) + (jt + r) * DH_ + c4;
        #pragma unroll
        for (int s = 0; s < 4; s++) {
            float4 a = *(const float4*)(arow + s * 16);
            int jj = s * 16 + c4;
            As[jj + 0][r] = a.x; As[jj + 1][r] = a.y; As[jj + 2][r] = a.z; As[jj + 3][r] = a.w;
            float4 b = *(const float4*)(vrow + s * 16);
            *(float4*)&Bs[r][s * 16 + c4] = b;
        }
        __syncthreads();
        #pragma unroll 8
        for (int k = 0; k < 64; k++) {
            float4 a = *(const float4*)&As[k][ty * 4];
            float4 b = *(const float4*)&Bs[k][tx * 4];
            float av[4] = {a.x, a.y, a.z, a.w};
            float bv[4] = {b.x, b.y, b.z, b.w};
            #pragma unroll
            for (int i = 0; i < 4; i++)
                #pragma unroll
                for (int j = 0; j < 4; j++)
                    acc[i][j] += av[i] * bv[j];
        }
        __syncthreads();
    }

    #pragma unroll
    for (int i = 0; i < 4; i++) {
        float4 o = make_float4(acc[i][0], acc[i][1], acc[i][2], acc[i][3]);
        *(float4*)(g_z + hm * (L_ * DH_) + (it + ty * 4 + i) * DH_ + tx * 4) = o;
    }
}

// ---------------------------------------------------------------------------
// Kernel 4b: z += alpha_i @ aV[i]   blocked by query position i.
// grid (hm_t=8, i=256). 64hm x 64d tile, loop j in chunks of 64.
// ---------------------------------------------------------------------------
__global__ __launch_bounds__(256) void z2_kernel(const float* __restrict__ aV)
{
    int hm0 = blockIdx.x * 64;
    int i   = blockIdx.y;

    __shared__ float As[64][64];   // [j][hm]
    __shared__ float Bs[64][64];   // [j][d]

    int tid = threadIdx.x;
    int r  = tid >> 2;
    int c4 = (tid & 3) * 4;
    int tx = tid & 15, ty = tid >> 4;

    float acc[4][4];
    #pragma unroll
    for (int a = 0; a < 4; a++)
        #pragma unroll
        for (int b = 0; b < 4; b++) acc[a][b] = 0.f;

    for (int jt = 0; jt < L_; jt += 64) {
        const float* arow = g_S + (hm0 + r) * (L_ * L_) + i * L_ + jt + c4;
        const float* brow = aV + (i * L_ + jt + r) * DH_ + c4;
        #pragma unroll
        for (int s = 0; s < 4; s++) {
            float4 a = *(const float4*)(arow + s * 16);
            int jj = s * 16 + c4;
            As[jj + 0][r] = a.x; As[jj + 1][r] = a.y; As[jj + 2][r] = a.z; As[jj + 3][r] = a.w;
            float4 b = *(const float4*)(brow + s * 16);
            *(float4*)&Bs[r][s * 16 + c4] = b;
        }
        __syncthreads();
        #pragma unroll 8
        for (int k = 0; k < 64; k++) {
            float4 a = *(const float4*)&As[k][ty * 4];
            float4 b = *(const float4*)&Bs[k][tx * 4];
            float av[4] = {a.x, a.y, a.z, a.w};
            float bv[4] = {b.x, b.y, b.z, b.w};
            #pragma unroll
            for (int ii = 0; ii < 4; ii++)
                #pragma unroll
                for (int jj = 0; jj < 4; jj++)
                    acc[ii][jj] += av[ii] * bv[jj];
        }
        __syncthreads();
    }

    #pragma unroll
    for (int ii = 0; ii < 4; ii++) {
        float* zp = g_z + (hm0 + ty * 4 + ii) * (L_ * DH_) + i * DH_ + tx * 4;
        float4 o = *(float4*)zp;
        o.x += acc[ii][0]; o.y += acc[ii][1]; o.z += acc[ii][2]; o.w += acc[ii][3];
        *(float4*)zp = o;
    }
}

// ---------------------------------------------------------------------------
// Kernel 5: out[i, h*64+d] = sum_m z[(h*64+m), i, d]
// ---------------------------------------------------------------------------
__global__ __launch_bounds__(512) void reduce_kernel(float* __restrict__ out)
{
    int i = blockIdx.x;      // 0..255
    int e = threadIdx.x;     // 0..511
    int h = e >> 6, d = e & 63;
    const float* p = g_z + (h * 64) * (L_ * DH_) + i * DH_ + d;
    float s = 0.f;
    #pragma unroll 8
    for (int m = 0; m < 64; m++) s += p[m * (L_ * DH_)];
    out[i * 512 + e] = s;
}

// ---------------------------------------------------------------------------
extern "C" void kernel_launch(void* const* d_in, const int* in_sizes, int n_in,
                              void* d_out, int out_size)
{
    const float* x  = (const float*)d_in[0];
    const float* Wq = (const float*)d_in[1];
    const float* Wk = (const float*)d_in[2];
    const float* Wv = (const float*)d_in[3];
    const float* aK = (const float*)d_in[4];
    const float* aV = (const float*)d_in[5];
    float* out = (float*)d_out;

    proj_kernel   <<<dim3(4, 128, 3), 256>>>(x, Wq, Wk, Wv);
    e1_kernel     <<<dim3(4, 4, 512), 256>>>();
    e2_kernel     <<<dim3(4, 8, 256), 256>>>(aK);
    softmax_kernel<<<dim3(HM_ * L_), 256>>>();
    z1_kernel     <<<dim3(4, 512), 256>>>();
    z2_kernel     <<<dim3(8, 256), 256>>>(aV);
    reduce_kernel <<<dim3(L_), 512>>>(out);
}

// round 7
// speedup vs baseline: 1.6141x; 1.6141x over previous
#include <cuda_runtime.h>
#include <cuda_bf16.h>
#include <math.h>
#include <stdint.h>

// Shapes (fixed): B=1, MSA=64, L=256, D=512, H=8, DH=64, HM = H*MSA = 512
#define HM_ 512
#define L_ 256
#define DH_ 64

// Scratch in device globals (allocation-free rule).
__device__ float g_q[HM_ * L_ * DH_];
__device__ float g_k[HM_ * L_ * DH_];
__device__ float g_v[HM_ * L_ * DH_];
__device__ float g_z[HM_ * L_ * DH_];
__device__ float g_S[HM_ * L_ * L_];

// bf16 hi/lo splits for tensor-core projection
__device__ __nv_bfloat16 g_xhi[16384 * 512];
__device__ __nv_bfloat16 g_xlo[16384 * 512];
__device__ __nv_bfloat16 g_whi[3 * 512 * 512];
__device__ __nv_bfloat16 g_wlo[3 * 512 * 512];

// ---------------------------------------------------------------------------
// helpers
// ---------------------------------------------------------------------------
__device__ __forceinline__ uint32_t smem_u32(const void* p) {
    uint32_t a;
    asm("{ .reg .u64 t; cvta.to.shared.u64 t, %1; cvt.u32.u64 %0, t; }" : "=r"(a) : "l"(p));
    return a;
}
__device__ __forceinline__ void ldm_x4(uint32_t* r, uint32_t addr) {
    asm volatile("ldmatrix.sync.aligned.m8n8.x4.shared.b16 {%0,%1,%2,%3}, [%4];"
                 : "=r"(r[0]), "=r"(r[1]), "=r"(r[2]), "=r"(r[3]) : "r"(addr));
}
__device__ __forceinline__ void mma_bf16(float* d, const uint32_t* a, const uint32_t* b) {
    asm volatile(
        "mma.sync.aligned.m16n8k16.row.col.f32.bf16.bf16.f32 "
        "{%0,%1,%2,%3}, {%4,%5,%6,%7}, {%8,%9}, {%0,%1,%2,%3};"
        : "+f"(d[0]), "+f"(d[1]), "+f"(d[2]), "+f"(d[3])
        : "r"(a[0]), "r"(a[1]), "r"(a[2]), "r"(a[3]), "r"(b[0]), "r"(b[1]));
}

// ---------------------------------------------------------------------------
// Kernel 0: split fp32 -> bf16 hi + lo
// ---------------------------------------------------------------------------
__global__ __launch_bounds__(256) void split_kernel(
    const float* __restrict__ src, __nv_bfloat16* __restrict__ hi,
    __nv_bfloat16* __restrict__ lo, int n)
{
    int idx = (blockIdx.x * 256 + threadIdx.x) * 4;
    if (idx >= n) return;
    float4 v = *(const float4*)(src + idx);
    __nv_bfloat16 h0 = __float2bfloat16_rn(v.x);
    __nv_bfloat16 h1 = __float2bfloat16_rn(v.y);
    __nv_bfloat16 h2 = __float2bfloat16_rn(v.z);
    __nv_bfloat16 h3 = __float2bfloat16_rn(v.w);
    __nv_bfloat16 l0 = __float2bfloat16_rn(v.x - __bfloat162float(h0));
    __nv_bfloat16 l1 = __float2bfloat16_rn(v.y - __bfloat162float(h1));
    __nv_bfloat16 l2 = __float2bfloat16_rn(v.z - __bfloat162float(h2));
    __nv_bfloat16 l3 = __float2bfloat16_rn(v.w - __bfloat162float(h3));
    __nv_bfloat162 hp0(h0, h1), hp1(h2, h3), lp0(l0, l1), lp1(l2, l3);
    *(uint2*)(hi + idx) = make_uint2(*(uint32_t*)&hp0, *(uint32_t*)&hp1);
    *(uint2*)(lo + idx) = make_uint2(*(uint32_t*)&lp0, *(uint32_t*)&lp1);
}

// ---------------------------------------------------------------------------
// Kernel 1: QKV projection via mma.sync bf16 (hi/lo 3-pass, fp32 accum).
// Y[m,n] = sum_k X[m,k] W[n,k].  Block tile 128m x 128n, K chunks of 32.
// 8 warps, each 64m x 32n (4x4 grid of m16n8k16 mma).
// grid (n=4, m=128, w=3), 256 threads.
// ---------------------------------------------------------------------------
__global__ __launch_bounds__(256) void proj_mma_kernel()
{
    __shared__ __nv_bfloat16 sAh[128][40];
    __shared__ __nv_bfloat16 sAl[128][40];
    __shared__ __nv_bfloat16 sBh[128][40];
    __shared__ __nv_bfloat16 sBl[128][40];

    int tid = threadIdx.x;
    int lane = tid & 31, wid = tid >> 5;
    int wr = wid >> 2, wc = wid & 3;     // warp row (0-1) x col (0-3)

    int n0 = blockIdx.x * 128;
    int m0 = blockIdx.y * 128;
    int wsel = blockIdx.z;

    const __nv_bfloat16* Bhg = g_whi + (size_t)wsel * 512 * 512;
    const __nv_bfloat16* Blg = g_wlo + (size_t)wsel * 512 * 512;
    float* Y = (wsel == 0) ? g_q : (wsel == 1) ? g_k : g_v;

    float acc[4][4][4];
    #pragma unroll
    for (int a = 0; a < 4; a++)
        #pragma unroll
        for (int b = 0; b < 4; b++)
            #pragma unroll
            for (int c = 0; c < 4; c++) acc[a][b][c] = 0.f;

    // ldmatrix per-lane base addresses
    int rowA = wr * 64 + (lane & 15);
    int colA = (lane >> 4) * 8;
    uint32_t aAh = smem_u32(&sAh[rowA][colA]);
    uint32_t aAl = smem_u32(&sAl[rowA][colA]);
    int rowB = wc * 32 + (lane & 7) + ((lane >> 4) << 3);
    int colB = ((lane >> 3) & 1) * 8;
    uint32_t aBh = smem_u32(&sBh[rowB][colB]);
    uint32_t aBl = smem_u32(&sBl[rowB][colB]);

    for (int kt = 0; kt < 16; kt++) {
        int k0 = kt * 32;
        // 128 rows x 32 k-elements per tile; 16-byte (8 bf16) chunks.
        // 128 rows * 4 chunks = 512 chunks = 256 threads * 2 iterations.
        #pragma unroll
        for (int it = 0; it < 2; it++) {
            int idx = tid + 256 * it;
            int row = idx >> 2, cg = (idx & 3) * 8;
            *(uint4*)&sAh[row][cg] = *(const uint4*)(g_xhi + (size_t)(m0 + row) * 512 + k0 + cg);
            *(uint4*)&sAl[row][cg] = *(const uint4*)(g_xlo + (size_t)(m0 + row) * 512 + k0 + cg);
            *(uint4*)&sBh[row][cg] = *(const uint4*)(Bhg + (size_t)(n0 + row) * 512 + k0 + cg);
            *(uint4*)&sBl[row][cg] = *(const uint4*)(Blg + (size_t)(n0 + row) * 512 + k0 + cg);
        }
        __syncthreads();

        #pragma unroll
        for (int ks = 0; ks < 2; ks++) {
            uint32_t ah[4][4], al[4][4], bh[4][2], bl[4][2];
            #pragma unroll
            for (int mt = 0; mt < 4; mt++) {
                uint32_t off = (uint32_t)(mt * 16 * 40 + ks * 16) * 2;
                ldm_x4(ah[mt], aAh + off);
                ldm_x4(al[mt], aAl + off);
            }
            #pragma unroll
            for (int np = 0; np < 2; np++) {
                uint32_t off = (uint32_t)(np * 16 * 40 + ks * 16) * 2;
                uint32_t t[4];
                ldm_x4(t, aBh + off);
                bh[np * 2][0] = t[0]; bh[np * 2][1] = t[1];
                bh[np * 2 + 1][0] = t[2]; bh[np * 2 + 1][1] = t[3];
                ldm_x4(t, aBl + off);
                bl[np * 2][0] = t[0]; bl[np * 2][1] = t[1];
                bl[np * 2 + 1][0] = t[2]; bl[np * 2 + 1][1] = t[3];
            }
            #pragma unroll
            for (int mt = 0; mt < 4; mt++) {
                #pragma unroll
                for (int nt = 0; nt < 4; nt++) {
                    mma_bf16(acc[mt][nt], ah[mt], bh[nt]);  // hi*hi
                    mma_bf16(acc[mt][nt], ah[mt], bl[nt]);  // hi*lo
                    mma_bf16(acc[mt][nt], al[mt], bh[nt]);  // lo*hi
                }
            }
        }
        __syncthreads();
    }

    // Epilogue: scatter into head-split layout [(h*64+msa)][i][d]
    #pragma unroll
    for (int mt = 0; mt < 4; mt++) {
        #pragma unroll
        for (int nt = 0; nt < 4; nt++) {
            int m_lo = m0 + wr * 64 + mt * 16 + (lane >> 2);
            int n = n0 + wc * 32 + nt * 8 + (lane & 3) * 2;
            int h = n >> 6, d = n & 63;
            int msa0 = m_lo >> 8, i0 = m_lo & 255;
            float* p0 = Y + ((size_t)(h * 64 + msa0) * 256 + i0) * 64 + d;
            *(float2*)p0 = make_float2(acc[mt][nt][0], acc[mt][nt][1]);
            int m_hi = m_lo + 8;
            int msa1 = m_hi >> 8, i1 = m_hi & 255;
            float* p1 = Y + ((size_t)(h * 64 + msa1) * 256 + i1) * 64 + d;
            *(float2*)p1 = make_float2(acc[mt][nt][2], acc[mt][nt][3]);
        }
    }
}

// ---------------------------------------------------------------------------
// Kernel 2a: e1 = (q @ k^T) * scale  ->  S
// ---------------------------------------------------------------------------
__global__ __launch_bounds__(256) void e1_kernel()
{
    int hm = blockIdx.z;
    int it = blockIdx.y * 64;
    int jt = blockIdx.x * 64;

    __shared__ float Qs[64][64];
    __shared__ float Ks[64][64];

    int tid = threadIdx.x;
    int r = tid >> 2;
    int c4 = (tid & 3) * 4;
    const float* qrow = g_q + hm * (L_ * DH_) + (it + r) * DH_ + c4;
    const float* krow = g_k + hm * (L_ * DH_) + (jt + r) * DH_ + c4;
    #pragma unroll
    for (int s = 0; s < 4; s++) {
        float4 a = *(const float4*)(qrow + s * 16);
        float4 b = *(const float4*)(krow + s * 16);
        int kk = s * 16 + c4;
        Qs[kk + 0][r] = a.x; Qs[kk + 1][r] = a.y; Qs[kk + 2][r] = a.z; Qs[kk + 3][r] = a.w;
        Ks[kk + 0][r] = b.x; Ks[kk + 1][r] = b.y; Ks[kk + 2][r] = b.z; Ks[kk + 3][r] = b.w;
    }
    __syncthreads();

    int tx = tid & 15, ty = tid >> 4;
    float acc[4][4];
    #pragma unroll
    for (int i = 0; i < 4; i++)
        #pragma unroll
        for (int j = 0; j < 4; j++) acc[i][j] = 0.f;

    #pragma unroll 8
    for (int k = 0; k < 64; k++) {
        float4 a = *(const float4*)&Qs[k][ty * 4];
        float4 b = *(const float4*)&Ks[k][tx * 4];
        float av[4] = {a.x, a.y, a.z, a.w};
        float bv[4] = {b.x, b.y, b.z, b.w};
        #pragma unroll
        for (int i = 0; i < 4; i++)
            #pragma unroll
            for (int j = 0; j < 4; j++)
                acc[i][j] += av[i] * bv[j];
    }

    const float scale = 0.125f;
    #pragma unroll
    for (int i = 0; i < 4; i++) {
        float4 o = make_float4(acc[i][0] * scale, acc[i][1] * scale,
                               acc[i][2] * scale, acc[i][3] * scale);
        *(float4*)(g_S + hm * (L_ * L_) + (it + ty * 4 + i) * L_ + jt + tx * 4) = o;
    }
}

// ---------------------------------------------------------------------------
// Kernel 2b: S += scale * (q_i @ aK[i]^T)
// ---------------------------------------------------------------------------
__global__ __launch_bounds__(256) void e2_kernel(const float* __restrict__ aK)
{
    int i = blockIdx.z;
    int hm0 = blockIdx.y * 64;
    int jt = blockIdx.x * 64;

    __shared__ float Qs[64][64];
    __shared__ float Bs[64][64];

    int tid = threadIdx.x;
    int r = tid >> 2;
    int c4 = (tid & 3) * 4;
    const float* qrow = g_q + (hm0 + r) * (L_ * DH_) + i * DH_ + c4;
    const float* arow = aK + (i * L_ + jt + r) * DH_ + c4;
    #pragma unroll
    for (int s = 0; s < 4; s++) {
        float4 a = *(const float4*)(qrow + s * 16);
        float4 b = *(const float4*)(arow + s * 16);
        int kk = s * 16 + c4;
        Qs[kk + 0][r] = a.x; Qs[kk + 1][r] = a.y; Qs[kk + 2][r] = a.z; Qs[kk + 3][r] = a.w;
        Bs[kk + 0][r] = b.x; Bs[kk + 1][r] = b.y; Bs[kk + 2][r] = b.z; Bs[kk + 3][r] = b.w;
    }
    __syncthreads();

    int tx = tid & 15, ty = tid >> 4;
    float acc[4][4];
    #pragma unroll
    for (int a = 0; a < 4; a++)
        #pragma unroll
        for (int b = 0; b < 4; b++) acc[a][b] = 0.f;

    #pragma unroll 8
    for (int k = 0; k < 64; k++) {
        float4 a = *(const float4*)&Qs[k][ty * 4];
        float4 b = *(const float4*)&Bs[k][tx * 4];
        float av[4] = {a.x, a.y, a.z, a.w};
        float bv[4] = {b.x, b.y, b.z, b.w};
        #pragma unroll
        for (int ii = 0; ii < 4; ii++)
            #pragma unroll
            for (int jj = 0; jj < 4; jj++)
                acc[ii][jj] += av[ii] * bv[jj];
    }

    const float scale = 0.125f;
    #pragma unroll
    for (int ii = 0; ii < 4; ii++) {
        float* Sp = g_S + (hm0 + ty * 4 + ii) * (L_ * L_) + i * L_ + jt + tx * 4;
        float4 o = *(float4*)Sp;
        o.x += acc[ii][0] * scale; o.y += acc[ii][1] * scale;
        o.z += acc[ii][2] * scale; o.w += acc[ii][3] * scale;
        *(float4*)Sp = o;
    }
}

// ---------------------------------------------------------------------------
// Kernel 3: row softmax. Warp per row, 8 rows per block, float4 loads.
// ---------------------------------------------------------------------------
__global__ __launch_bounds__(256) void softmax_kernel()
{
    int row = blockIdx.x * 8 + (threadIdx.x >> 5);
    int l = threadIdx.x & 31;
    float4* p = (float4*)(g_S + (size_t)row * L_);
    float4 a = p[l];
    float4 b = p[l + 32];

    float m = fmaxf(fmaxf(fmaxf(a.x, a.y), fmaxf(a.z, a.w)),
                    fmaxf(fmaxf(b.x, b.y), fmaxf(b.z, b.w)));
    #pragma unroll
    for (int o = 16; o > 0; o >>= 1) m = fmaxf(m, __shfl_xor_sync(0xffffffffu, m, o));

    a.x = __expf(a.x - m); a.y = __expf(a.y - m); a.z = __expf(a.z - m); a.w = __expf(a.w - m);
    b.x = __expf(b.x - m); b.y = __expf(b.y - m); b.z = __expf(b.z - m); b.w = __expf(b.w - m);

    float s = (a.x + a.y) + (a.z + a.w) + (b.x + b.y) + (b.z + b.w);
    #pragma unroll
    for (int o = 16; o > 0; o >>= 1) s += __shfl_xor_sync(0xffffffffu, s, o);

    float inv = 1.0f / s;
    a.x *= inv; a.y *= inv; a.z *= inv; a.w *= inv;
    b.x *= inv; b.y *= inv; b.z *= inv; b.w *= inv;
    p[l] = a;
    p[l + 32] = b;
}

// ---------------------------------------------------------------------------
// Kernel 4a: z = alpha @ v
// ---------------------------------------------------------------------------
__global__ __launch_bounds__(256) void z1_kernel()
{
    int hm = blockIdx.y;
    int it = blockIdx.x * 64;

    __shared__ float As[64][64];
    __shared__ float Bs[64][64];

    int tid = threadIdx.x;
    int r = tid >> 2;
    int c4 = (tid & 3) * 4;
    int tx = tid & 15, ty = tid >> 4;

    float acc[4][4];
    #pragma unroll
    for (int i = 0; i < 4; i++)
        #pragma unroll
        for (int j = 0; j < 4; j++) acc[i][j] = 0.f;

    for (int jt = 0; jt < L_; jt += 64) {
        const float* arow = g_S + hm * (L_ * L_) + (it + r) * L_ + jt + c4;
        const float* vrow = g_v + hm * (L_ * DH_) + (jt + r) * DH_ + c4;
        #pragma unroll
        for (int s = 0; s < 4; s++) {
            float4 a = *(const float4*)(arow + s * 16);
            int jj = s * 16 + c4;
            As[jj + 0][r] = a.x; As[jj + 1][r] = a.y; As[jj + 2][r] = a.z; As[jj + 3][r] = a.w;
            float4 b = *(const float4*)(vrow + s * 16);
            *(float4*)&Bs[r][s * 16 + c4] = b;
        }
        __syncthreads();
        #pragma unroll 8
        for (int k = 0; k < 64; k++) {
            float4 a = *(const float4*)&As[k][ty * 4];
            float4 b = *(const float4*)&Bs[k][tx * 4];
            float av[4] = {a.x, a.y, a.z, a.w};
            float bv[4] = {b.x, b.y, b.z, b.w};
            #pragma unroll
            for (int i = 0; i < 4; i++)
                #pragma unroll
                for (int j = 0; j < 4; j++)
                    acc[i][j] += av[i] * bv[j];
        }
        __syncthreads();
    }

    #pragma unroll
    for (int i = 0; i < 4; i++) {
        float4 o = make_float4(acc[i][0], acc[i][1], acc[i][2], acc[i][3]);
        *(float4*)(g_z + hm * (L_ * DH_) + (it + ty * 4 + i) * DH_ + tx * 4) = o;
    }
}

// ---------------------------------------------------------------------------
// Kernel 4b: z += alpha_i @ aV[i]
// ---------------------------------------------------------------------------
__global__ __launch_bounds__(256) void z2_kernel(const float* __restrict__ aV)
{
    int hm0 = blockIdx.x * 64;
    int i = blockIdx.y;

    __shared__ float As[64][64];
    __shared__ float Bs[64][64];

    int tid = threadIdx.x;
    int r = tid >> 2;
    int c4 = (tid & 3) * 4;
    int tx = tid & 15, ty = tid >> 4;

    float acc[4][4];
    #pragma unroll
    for (int a = 0; a < 4; a++)
        #pragma unroll
        for (int b = 0; b < 4; b++) acc[a][b] = 0.f;

    for (int jt = 0; jt < L_; jt += 64) {
        const float* arow = g_S + (hm0 + r) * (L_ * L_) + i * L_ + jt + c4;
        const float* brow = aV + (i * L_ + jt + r) * DH_ + c4;
        #pragma unroll
        for (int s = 0; s < 4; s++) {
            float4 a = *(const float4*)(arow + s * 16);
            int jj = s * 16 + c4;
            As[jj + 0][r] = a.x; As[jj + 1][r] = a.y; As[jj + 2][r] = a.z; As[jj + 3][r] = a.w;
            float4 b = *(const float4*)(brow + s * 16);
            *(float4*)&Bs[r][s * 16 + c4] = b;
        }
        __syncthreads();
        #pragma unroll 8
        for (int k = 0; k < 64; k++) {
            float4 a = *(const float4*)&As[k][ty * 4];
            float4 b = *(const float4*)&Bs[k][tx * 4];
            float av[4] = {a.x, a.y, a.z, a.w};
            float bv[4] = {b.x, b.y, b.z, b.w};
            #pragma unroll
            for (int ii = 0; ii < 4; ii++)
                #pragma unroll
                for (int jj = 0; jj < 4; jj++)
                    acc[ii][jj] += av[ii] * bv[jj];
        }
        __syncthreads();
    }

    #pragma unroll
    for (int ii = 0; ii < 4; ii++) {
        float* zp = g_z + (hm0 + ty * 4 + ii) * (L_ * DH_) + i * DH_ + tx * 4;
        float4 o = *(float4*)zp;
        o.x += acc[ii][0]; o.y += acc[ii][1]; o.z += acc[ii][2]; o.w += acc[ii][3];
        *(float4*)zp = o;
    }
}

// ---------------------------------------------------------------------------
// Kernel 5: out[i, h*64+d] = sum_m z[(h*64+m), i, d]
// ---------------------------------------------------------------------------
__global__ __launch_bounds__(512) void reduce_kernel(float* __restrict__ out)
{
    int i = blockIdx.x;
    int e = threadIdx.x;
    int h = e >> 6, d = e & 63;
    const float* p = g_z + (h * 64) * (L_ * DH_) + i * DH_ + d;
    float s = 0.f;
    #pragma unroll 8
    for (int m = 0; m < 64; m++) s += p[m * (L_ * DH_)];
    out[i * 512 + e] = s;
}

// ---------------------------------------------------------------------------
extern "C" void kernel_launch(void* const* d_in, const int* in_sizes, int n_in,
                              void* d_out, int out_size)
{
    const float* x  = (const float*)d_in[0];
    const float* Wq = (const float*)d_in[1];
    const float* Wk = (const float*)d_in[2];
    const float* Wv = (const float*)d_in[3];
    const float* aK = (const float*)d_in[4];
    const float* aV = (const float*)d_in[5];
    float* out = (float*)d_out;

    static __nv_bfloat16 *xhi = nullptr, *xlo = nullptr, *whi = nullptr, *wlo = nullptr;
    if (!xhi) {
        cudaGetSymbolAddress((void**)&xhi, g_xhi);
        cudaGetSymbolAddress((void**)&xlo, g_xlo);
        cudaGetSymbolAddress((void**)&whi, g_whi);
        cudaGetSymbolAddress((void**)&wlo, g_wlo);
    }

    // split inputs to bf16 hi/lo
    split_kernel<<<8192, 256>>>(x, xhi, xlo, 16384 * 512);
    split_kernel<<<256, 256>>>(Wq, whi, wlo, 512 * 512);
    split_kernel<<<256, 256>>>(Wk, whi + 512 * 512, wlo + 512 * 512, 512 * 512);
    split_kernel<<<256, 256>>>(Wv, whi + 2 * 512 * 512, wlo + 2 * 512 * 512, 512 * 512);

    proj_mma_kernel<<<dim3(4, 128, 3), 256>>>();
    e1_kernel     <<<dim3(4, 4, 512), 256>>>();
    e2_kernel     <<<dim3(4, 8, 256), 256>>>(aK);
    softmax_kernel<<<dim3(HM_ * L_ / 8), 256>>>();
    z1_kernel     <<<dim3(4, 512), 256>>>();
    z2_kernel     <<<dim3(8, 256), 256>>>(aV);
    reduce_kernel <<<dim3(L_), 512>>>(out);
}

// round 8
// speedup vs baseline: 2.2496x; 1.3937x over previous
#include <cuda_runtime.h>
#include <cuda_bf16.h>
#include <math.h>
#include <stdint.h>

// Shapes (fixed): B=1, MSA=64, L=256, D=512, H=8, DH=64, HM = H*MSA = 512
#define HM_ 512
#define L_ 256
#define DH_ 64

// Scratch in device globals (allocation-free rule).
__device__ float g_q[HM_ * L_ * DH_];
__device__ float g_k[HM_ * L_ * DH_];
__device__ float g_v[HM_ * L_ * DH_];
__device__ float g_z[HM_ * L_ * DH_];
__device__ float g_S[HM_ * L_ * L_];

// bf16 hi/lo splits for tensor-core projection
__device__ __nv_bfloat16 g_xhi[16384 * 512];
__device__ __nv_bfloat16 g_xlo[16384 * 512];
__device__ __nv_bfloat16 g_whi[3 * 512 * 512];
__device__ __nv_bfloat16 g_wlo[3 * 512 * 512];

// ---------------------------------------------------------------------------
// helpers
// ---------------------------------------------------------------------------
__device__ __forceinline__ uint32_t smem_u32(const void* p) {
    uint32_t a;
    asm("{ .reg .u64 t; cvta.to.shared.u64 t, %1; cvt.u32.u64 %0, t; }" : "=r"(a) : "l"(p));
    return a;
}
__device__ __forceinline__ void ldm_x4(uint32_t* r, uint32_t addr) {
    asm volatile("ldmatrix.sync.aligned.m8n8.x4.shared.b16 {%0,%1,%2,%3}, [%4];"
                 : "=r"(r[0]), "=r"(r[1]), "=r"(r[2]), "=r"(r[3]) : "r"(addr));
}
__device__ __forceinline__ void ldm_x4_trans(uint32_t* r, uint32_t addr) {
    asm volatile("ldmatrix.sync.aligned.m8n8.x4.trans.shared.b16 {%0,%1,%2,%3}, [%4];"
                 : "=r"(r[0]), "=r"(r[1]), "=r"(r[2]), "=r"(r[3]) : "r"(addr));
}
__device__ __forceinline__ void mma_bf16(float* d, const uint32_t* a, const uint32_t* b) {
    asm volatile(
        "mma.sync.aligned.m16n8k16.row.col.f32.bf16.bf16.f32 "
        "{%0,%1,%2,%3}, {%4,%5,%6,%7}, {%8,%9}, {%0,%1,%2,%3};"
        : "+f"(d[0]), "+f"(d[1]), "+f"(d[2]), "+f"(d[3])
        : "r"(a[0]), "r"(a[1]), "r"(a[2]), "r"(a[3]), "r"(b[0]), "r"(b[1]));
}
// fp32 float4 -> hi/lo bf16x4 stored to smem (16B-spaced chunks, 8B stores)
__device__ __forceinline__ void cvt_store(float4 v, __nv_bfloat16* ph, __nv_bfloat16* pl) {
    __nv_bfloat16 h0 = __float2bfloat16_rn(v.x), h1 = __float2bfloat16_rn(v.y),
                  h2 = __float2bfloat16_rn(v.z), h3 = __float2bfloat16_rn(v.w);
    __nv_bfloat16 l0 = __float2bfloat16_rn(v.x - __bfloat162float(h0)),
                  l1 = __float2bfloat16_rn(v.y - __bfloat162float(h1)),
                  l2 = __float2bfloat16_rn(v.z - __bfloat162float(h2)),
                  l3 = __float2bfloat16_rn(v.w - __bfloat162float(h3));
    __nv_bfloat162 hp0(h0, h1), hp1(h2, h3), lp0(l0, l1), lp1(l2, l3);
    *(uint2*)ph = make_uint2(*(uint32_t*)&hp0, *(uint32_t*)&hp1);
    *(uint2*)pl = make_uint2(*(uint32_t*)&lp0, *(uint32_t*)&lp1);
}

// ---------------------------------------------------------------------------
// Kernel 0: split fp32 -> bf16 hi + lo (for projection inputs)
// ---------------------------------------------------------------------------
__global__ __launch_bounds__(256) void split_kernel(
    const float* __restrict__ src, __nv_bfloat16* __restrict__ hi,
    __nv_bfloat16* __restrict__ lo, int n)
{
    int idx = (blockIdx.x * 256 + threadIdx.x) * 4;
    if (idx >= n) return;
    float4 v = *(const float4*)(src + idx);
    cvt_store(v, hi + idx, lo + idx);
}

// ---------------------------------------------------------------------------
// Kernel 1: QKV projection via mma.sync bf16 (hi/lo 3-pass, fp32 accum).
// ---------------------------------------------------------------------------
__global__ __launch_bounds__(256) void proj_mma_kernel()
{
    __shared__ __nv_bfloat16 sAh[128][40];
    __shared__ __nv_bfloat16 sAl[128][40];
    __shared__ __nv_bfloat16 sBh[128][40];
    __shared__ __nv_bfloat16 sBl[128][40];

    int tid = threadIdx.x;
    int lane = tid & 31, wid = tid >> 5;
    int wr = wid >> 2, wc = wid & 3;

    int n0 = blockIdx.x * 128;
    int m0 = blockIdx.y * 128;
    int wsel = blockIdx.z;

    const __nv_bfloat16* Bhg = g_whi + (size_t)wsel * 512 * 512;
    const __nv_bfloat16* Blg = g_wlo + (size_t)wsel * 512 * 512;
    float* Y = (wsel == 0) ? g_q : (wsel == 1) ? g_k : g_v;

    float acc[4][4][4];
    #pragma unroll
    for (int a = 0; a < 4; a++)
        #pragma unroll
        for (int b = 0; b < 4; b++)
            #pragma unroll
            for (int c = 0; c < 4; c++) acc[a][b][c] = 0.f;

    int rowA = wr * 64 + (lane & 15);
    int colA = (lane >> 4) * 8;
    uint32_t aAh = smem_u32(&sAh[rowA][colA]);
    uint32_t aAl = smem_u32(&sAl[rowA][colA]);
    int rowB = wc * 32 + (lane & 7) + ((lane >> 4) << 3);
    int colB = ((lane >> 3) & 1) * 8;
    uint32_t aBh = smem_u32(&sBh[rowB][colB]);
    uint32_t aBl = smem_u32(&sBl[rowB][colB]);

    for (int kt = 0; kt < 16; kt++) {
        int k0 = kt * 32;
        #pragma unroll
        for (int it = 0; it < 2; it++) {
            int idx = tid + 256 * it;
            int row = idx >> 2, cg = (idx & 3) * 8;
            *(uint4*)&sAh[row][cg] = *(const uint4*)(g_xhi + (size_t)(m0 + row) * 512 + k0 + cg);
            *(uint4*)&sAl[row][cg] = *(const uint4*)(g_xlo + (size_t)(m0 + row) * 512 + k0 + cg);
            *(uint4*)&sBh[row][cg] = *(const uint4*)(Bhg + (size_t)(n0 + row) * 512 + k0 + cg);
            *(uint4*)&sBl[row][cg] = *(const uint4*)(Blg + (size_t)(n0 + row) * 512 + k0 + cg);
        }
        __syncthreads();

        #pragma unroll
        for (int ks = 0; ks < 2; ks++) {
            uint32_t ah[4][4], al[4][4], bh[4][2], bl[4][2];
            #pragma unroll
            for (int mt = 0; mt < 4; mt++) {
                uint32_t off = (uint32_t)(mt * 16 * 40 + ks * 16) * 2;
                ldm_x4(ah[mt], aAh + off);
                ldm_x4(al[mt], aAl + off);
            }
            #pragma unroll
            for (int np = 0; np < 2; np++) {
                uint32_t off = (uint32_t)(np * 16 * 40 + ks * 16) * 2;
                uint32_t t[4];
                ldm_x4(t, aBh + off);
                bh[np * 2][0] = t[0]; bh[np * 2][1] = t[1];
                bh[np * 2 + 1][0] = t[2]; bh[np * 2 + 1][1] = t[3];
                ldm_x4(t, aBl + off);
                bl[np * 2][0] = t[0]; bl[np * 2][1] = t[1];
                bl[np * 2 + 1][0] = t[2]; bl[np * 2 + 1][1] = t[3];
            }
            #pragma unroll
            for (int mt = 0; mt < 4; mt++) {
                #pragma unroll
                for (int nt = 0; nt < 4; nt++) {
                    mma_bf16(acc[mt][nt], ah[mt], bh[nt]);
                    mma_bf16(acc[mt][nt], ah[mt], bl[nt]);
                    mma_bf16(acc[mt][nt], al[mt], bh[nt]);
                }
            }
        }
        __syncthreads();
    }

    #pragma unroll
    for (int mt = 0; mt < 4; mt++) {
        #pragma unroll
        for (int nt = 0; nt < 4; nt++) {
            int m_lo = m0 + wr * 64 + mt * 16 + (lane >> 2);
            int n = n0 + wc * 32 + nt * 8 + (lane & 3) * 2;
            int h = n >> 6, d = n & 63;
            int msa0 = m_lo >> 8, i0 = m_lo & 255;
            float* p0 = Y + ((size_t)(h * 64 + msa0) * 256 + i0) * 64 + d;
            *(float2*)p0 = make_float2(acc[mt][nt][0], acc[mt][nt][1]);
            int m_hi = m_lo + 8;
            int msa1 = m_hi >> 8, i1 = m_hi & 255;
            float* p1 = Y + ((size_t)(h * 64 + msa1) * 256 + i1) * 64 + d;
            *(float2*)p1 = make_float2(acc[mt][nt][2], acc[mt][nt][3]);
        }
    }
}

// ---------------------------------------------------------------------------
// Kernel 2a: e1 = scale*(q @ k^T) -> S.  Per hm, 128i x 128j blocks, K=64.
// hi/lo split on the fly from fp32. grid (j=2, i=2, hm=512).
// ---------------------------------------------------------------------------
__global__ __launch_bounds__(256) void e1_mma_kernel()
{
    __shared__ __nv_bfloat16 sAh[128][40];
    __shared__ __nv_bfloat16 sAl[128][40];
    __shared__ __nv_bfloat16 sBh[128][40];
    __shared__ __nv_bfloat16 sBl[128][40];

    int tid = threadIdx.x;
    int lane = tid & 31, wid = tid >> 5;
    int wr = wid >> 2, wc = wid & 3;

    int j0 = blockIdx.x * 128;
    int i0 = blockIdx.y * 128;
    int hm = blockIdx.z;
    const float* qb = g_q + (size_t)hm * (L_ * DH_);
    const float* kb = g_k + (size_t)hm * (L_ * DH_);

    float acc[4][4][4];
    #pragma unroll
    for (int a = 0; a < 4; a++)
        #pragma unroll
        for (int b = 0; b < 4; b++)
            #pragma unroll
            for (int c = 0; c < 4; c++) acc[a][b][c] = 0.f;

    int rowA = wr * 64 + (lane & 15);
    int colA = (lane >> 4) * 8;
    uint32_t aAh = smem_u32(&sAh[rowA][colA]);
    uint32_t aAl = smem_u32(&sAl[rowA][colA]);
    int rowB = wc * 32 + (lane & 7) + ((lane >> 4) << 3);
    int colB = ((lane >> 3) & 1) * 8;
    uint32_t aBh = smem_u32(&sBh[rowB][colB]);
    uint32_t aBl = smem_u32(&sBl[rowB][colB]);

    for (int kt = 0; kt < 2; kt++) {
        int k0 = kt * 32;
        // 128 rows x 32 cols fp32 = 8 float4/row; 1024 chunks / 256 thr = 4 iters
        #pragma unroll
        for (int it = 0; it < 4; it++) {
            int idx = tid + 256 * it;
            int row = idx >> 3, cg = (idx & 7) * 4;
            float4 va = *(const float4*)(qb + (size_t)(i0 + row) * 64 + k0 + cg);
            cvt_store(va, &sAh[row][cg], &sAl[row][cg]);
            float4 vb = *(const float4*)(kb + (size_t)(j0 + row) * 64 + k0 + cg);
            cvt_store(vb, &sBh[row][cg], &sBl[row][cg]);
        }
        __syncthreads();

        #pragma unroll
        for (int ks = 0; ks < 2; ks++) {
            uint32_t ah[4][4], al[4][4], bh[4][2], bl[4][2];
            #pragma unroll
            for (int mt = 0; mt < 4; mt++) {
                uint32_t off = (uint32_t)(mt * 16 * 40 + ks * 16) * 2;
                ldm_x4(ah[mt], aAh + off);
                ldm_x4(al[mt], aAl + off);
            }
            #pragma unroll
            for (int np = 0; np < 2; np++) {
                uint32_t off = (uint32_t)(np * 16 * 40 + ks * 16) * 2;
                uint32_t t[4];
                ldm_x4(t, aBh + off);
                bh[np * 2][0] = t[0]; bh[np * 2][1] = t[1];
                bh[np * 2 + 1][0] = t[2]; bh[np * 2 + 1][1] = t[3];
                ldm_x4(t, aBl + off);
                bl[np * 2][0] = t[0]; bl[np * 2][1] = t[1];
                bl[np * 2 + 1][0] = t[2]; bl[np * 2 + 1][1] = t[3];
            }
            #pragma unroll
            for (int mt = 0; mt < 4; mt++) {
                #pragma unroll
                for (int nt = 0; nt < 4; nt++) {
                    mma_bf16(acc[mt][nt], ah[mt], bh[nt]);
                    mma_bf16(acc[mt][nt], ah[mt], bl[nt]);
                    mma_bf16(acc[mt][nt], al[mt], bh[nt]);
                }
            }
        }
        __syncthreads();
    }

    const float scale = 0.125f;
    float* Sb = g_S + (size_t)hm * (L_ * L_);
    #pragma unroll
    for (int mt = 0; mt < 4; mt++) {
        #pragma unroll
        for (int nt = 0; nt < 4; nt++) {
            int row = i0 + wr * 64 + mt * 16 + (lane >> 2);
            int col = j0 + wc * 32 + nt * 8 + (lane & 3) * 2;
            float* p = Sb + (size_t)row * 256 + col;
            *(float2*)p = make_float2(acc[mt][nt][0] * scale, acc[mt][nt][1] * scale);
            *(float2*)(p + 8 * 256) = make_float2(acc[mt][nt][2] * scale, acc[mt][nt][3] * scale);
        }
    }
}

// ---------------------------------------------------------------------------
// Kernel 2b: S += scale*(q_i @ aK[i]^T).  Per i, 128hm x 128j blocks, K=64.
// grid (j=2, hm=4, i=256).
// ---------------------------------------------------------------------------
__global__ __launch_bounds__(256) void e2_mma_kernel(const float* __restrict__ aK)
{
    __shared__ __nv_bfloat16 sAh[128][40];
    __shared__ __nv_bfloat16 sAl[128][40];
    __shared__ __nv_bfloat16 sBh[128][40];
    __shared__ __nv_bfloat16 sBl[128][40];

    int tid = threadIdx.x;
    int lane = tid & 31, wid = tid >> 5;
    int wr = wid >> 2, wc = wid & 3;

    int j0 = blockIdx.x * 128;
    int hm0 = blockIdx.y * 128;
    int i = blockIdx.z;
    const float* aKb = aK + (size_t)i * (L_ * DH_);

    float acc[4][4][4];
    #pragma unroll
    for (int a = 0; a < 4; a++)
        #pragma unroll
        for (int b = 0; b < 4; b++)
            #pragma unroll
            for (int c = 0; c < 4; c++) acc[a][b][c] = 0.f;

    int rowA = wr * 64 + (lane & 15);
    int colA = (lane >> 4) * 8;
    uint32_t aAh = smem_u32(&sAh[rowA][colA]);
    uint32_t aAl = smem_u32(&sAl[rowA][colA]);
    int rowB = wc * 32 + (lane & 7) + ((lane >> 4) << 3);
    int colB = ((lane >> 3) & 1) * 8;
    uint32_t aBh = smem_u32(&sBh[rowB][colB]);
    uint32_t aBl = smem_u32(&sBl[rowB][colB]);

    for (int kt = 0; kt < 2; kt++) {
        int k0 = kt * 32;
        #pragma unroll
        for (int it = 0; it < 4; it++) {
            int idx = tid + 256 * it;
            int row = idx >> 3, cg = (idx & 7) * 4;
            // A row = q[hm0+row] at position i
            float4 va = *(const float4*)(g_q + (size_t)(hm0 + row) * (L_ * DH_) + (size_t)i * 64 + k0 + cg);
            cvt_store(va, &sAh[row][cg], &sAl[row][cg]);
            float4 vb = *(const float4*)(aKb + (size_t)(j0 + row) * 64 + k0 + cg);
            cvt_store(vb, &sBh[row][cg], &sBl[row][cg]);
        }
        __syncthreads();

        #pragma unroll
        for (int ks = 0; ks < 2; ks++) {
            uint32_t ah[4][4], al[4][4], bh[4][2], bl[4][2];
            #pragma unroll
            for (int mt = 0; mt < 4; mt++) {
                uint32_t off = (uint32_t)(mt * 16 * 40 + ks * 16) * 2;
                ldm_x4(ah[mt], aAh + off);
                ldm_x4(al[mt], aAl + off);
            }
            #pragma unroll
            for (int np = 0; np < 2; np++) {
                uint32_t off = (uint32_t)(np * 16 * 40 + ks * 16) * 2;
                uint32_t t[4];
                ldm_x4(t, aBh + off);
                bh[np * 2][0] = t[0]; bh[np * 2][1] = t[1];
                bh[np * 2 + 1][0] = t[2]; bh[np * 2 + 1][1] = t[3];
                ldm_x4(t, aBl + off);
                bl[np * 2][0] = t[0]; bl[np * 2][1] = t[1];
                bl[np * 2 + 1][0] = t[2]; bl[np * 2 + 1][1] = t[3];
            }
            #pragma unroll
            for (int mt = 0; mt < 4; mt++) {
                #pragma unroll
                for (int nt = 0; nt < 4; nt++) {
                    mma_bf16(acc[mt][nt], ah[mt], bh[nt]);
                    mma_bf16(acc[mt][nt], ah[mt], bl[nt]);
                    mma_bf16(acc[mt][nt], al[mt], bh[nt]);
                }
            }
        }
        __syncthreads();
    }

    const float scale = 0.125f;
    #pragma unroll
    for (int mt = 0; mt < 4; mt++) {
        #pragma unroll
        for (int nt = 0; nt < 4; nt++) {
            int hmr = hm0 + wr * 64 + mt * 16 + (lane >> 2);
            int col = j0 + wc * 32 + nt * 8 + (lane & 3) * 2;
            float* p = g_S + (size_t)hmr * (L_ * L_) + (size_t)i * 256 + col;
            float2 o = *(float2*)p;
            o.x += acc[mt][nt][0] * scale; o.y += acc[mt][nt][1] * scale;
            *(float2*)p = o;
            float* p2 = p + (size_t)8 * (L_ * L_);
            float2 o2 = *(float2*)p2;
            o2.x += acc[mt][nt][2] * scale; o2.y += acc[mt][nt][3] * scale;
            *(float2*)p2 = o2;
        }
    }
}

// ---------------------------------------------------------------------------
// Kernel 3: row softmax. Warp per row, 8 rows per block, float4 loads.
// ---------------------------------------------------------------------------
__global__ __launch_bounds__(256) void softmax_kernel()
{
    int row = blockIdx.x * 8 + (threadIdx.x >> 5);
    int l = threadIdx.x & 31;
    float4* p = (float4*)(g_S + (size_t)row * L_);
    float4 a = p[l];
    float4 b = p[l + 32];

    float m = fmaxf(fmaxf(fmaxf(a.x, a.y), fmaxf(a.z, a.w)),
                    fmaxf(fmaxf(b.x, b.y), fmaxf(b.z, b.w)));
    #pragma unroll
    for (int o = 16; o > 0; o >>= 1) m = fmaxf(m, __shfl_xor_sync(0xffffffffu, m, o));

    a.x = __expf(a.x - m); a.y = __expf(a.y - m); a.z = __expf(a.z - m); a.w = __expf(a.w - m);
    b.x = __expf(b.x - m); b.y = __expf(b.y - m); b.z = __expf(b.z - m); b.w = __expf(b.w - m);

    float s = (a.x + a.y) + (a.z + a.w) + (b.x + b.y) + (b.z + b.w);
    #pragma unroll
    for (int o = 16; o > 0; o >>= 1) s += __shfl_xor_sync(0xffffffffu, s, o);

    float inv = 1.0f / s;
    a.x *= inv; a.y *= inv; a.z *= inv; a.w *= inv;
    b.x *= inv; b.y *= inv; b.z *= inv; b.w *= inv;
    p[l] = a;
    p[l + 32] = b;
}

// ---------------------------------------------------------------------------
// Kernel 4a: z = alpha @ v.  Per hm, 128i x 64d blocks, K=256 in 32-chunks.
// B fragments via ldmatrix.trans on natural [j][d] v tiles.
// grid (i-tiles=2, hm=512). 8 warps = 4(i) x 2(d), warp 32i x 32d.
// ---------------------------------------------------------------------------
__global__ __launch_bounds__(256) void z1_mma_kernel()
{
    __shared__ __nv_bfloat16 sAh[128][40];
    __shared__ __nv_bfloat16 sAl[128][40];
    __shared__ __nv_bfloat16 sBh[32][72];
    __shared__ __nv_bfloat16 sBl[32][72];

    int tid = threadIdx.x;
    int lane = tid & 31, wid = tid >> 5;
    int wi = wid >> 1, wd = wid & 1;

    int i0 = blockIdx.x * 128;
    int hm = blockIdx.y;
    const float* Ab = g_S + (size_t)hm * (L_ * L_);
    const float* Bb = g_v + (size_t)hm * (L_ * DH_);

    float acc[2][4][4];
    #pragma unroll
    for (int a = 0; a < 2; a++)
        #pragma unroll
        for (int b = 0; b < 4; b++)
            #pragma unroll
            for (int c = 0; c < 4; c++) acc[a][b][c] = 0.f;

    int rowA = wi * 32 + (lane & 15);
    int colA = (lane >> 4) * 8;
    uint32_t aAh = smem_u32(&sAh[rowA][colA]);
    uint32_t aAl = smem_u32(&sAl[rowA][colA]);
    // trans-B: lane points to row (k) of the [k][n] tile
    int rowBt = lane & 15;
    int colBt = wd * 32 + ((lane >> 4) << 3);
    uint32_t aBh = smem_u32(&sBh[rowBt][colBt]);
    uint32_t aBl = smem_u32(&sBl[rowBt][colBt]);

    for (int jt = 0; jt < 8; jt++) {
        int k0 = jt * 32;
        // A: alpha rows 128 x 32 cols; 1024 chunks / 256 = 4 iters
        #pragma unroll
        for (int it = 0; it < 4; it++) {
            int idx = tid + 256 * it;
            int row = idx >> 3, cg = (idx & 7) * 4;
            float4 va = *(const float4*)(Ab + (size_t)(i0 + row) * 256 + k0 + cg);
            cvt_store(va, &sAh[row][cg], &sAl[row][cg]);
        }
        // B: v rows 32 x 64 cols; 512 chunks / 256 = 2 iters
        #pragma unroll
        for (int it = 0; it < 2; it++) {
            int idx = tid + 256 * it;
            int jr = idx >> 4, cg = (idx & 15) * 4;
            float4 vb = *(const float4*)(Bb + (size_t)(k0 + jr) * 64 + cg);
            cvt_store(vb, &sBh[jr][cg], &sBl[jr][cg]);
        }
        __syncthreads();

        #pragma unroll
        for (int ks = 0; ks < 2; ks++) {
            uint32_t ah[2][4], al[2][4], bh[4][2], bl[4][2];
            #pragma unroll
            for (int mt = 0; mt < 2; mt++) {
                uint32_t off = (uint32_t)(mt * 16 * 40 + ks * 16) * 2;
                ldm_x4(ah[mt], aAh + off);
                ldm_x4(al[mt], aAl + off);
            }
            #pragma unroll
            for (int nn = 0; nn < 2; nn++) {
                uint32_t off = (uint32_t)(ks * 16 * 72 + nn * 16) * 2;
                uint32_t t[4];
                ldm_x4_trans(t, aBh + off);
                bh[nn * 2][0] = t[0]; bh[nn * 2][1] = t[1];
                bh[nn * 2 + 1][0] = t[2]; bh[nn * 2 + 1][1] = t[3];
                ldm_x4_trans(t, aBl + off);
                bl[nn * 2][0] = t[0]; bl[nn * 2][1] = t[1];
                bl[nn * 2 + 1][0] = t[2]; bl[nn * 2 + 1][1] = t[3];
            }
            #pragma unroll
            for (int mt = 0; mt < 2; mt++) {
                #pragma unroll
                for (int nt = 0; nt < 4; nt++) {
                    mma_bf16(acc[mt][nt], ah[mt], bh[nt]);
                    mma_bf16(acc[mt][nt], ah[mt], bl[nt]);
                    mma_bf16(acc[mt][nt], al[mt], bh[nt]);
                }
            }
        }
        __syncthreads();
    }

    float* Zb = g_z + (size_t)hm * (L_ * DH_);
    #pragma unroll
    for (int mt = 0; mt < 2; mt++) {
        #pragma unroll
        for (int nt = 0; nt < 4; nt++) {
            int row = i0 + wi * 32 + mt * 16 + (lane >> 2);
            int col = wd * 32 + nt * 8 + (lane & 3) * 2;
            float* p = Zb + (size_t)row * 64 + col;
            *(float2*)p = make_float2(acc[mt][nt][0], acc[mt][nt][1]);
            *(float2*)(p + 8 * 64) = make_float2(acc[mt][nt][2], acc[mt][nt][3]);
        }
    }
}

// ---------------------------------------------------------------------------
// Kernel 4b: z += alpha_i @ aV[i].  Per i, 128hm x 64d blocks, K=256.
// grid (hm-tiles=4, i=256). Same structure as z1.
// ---------------------------------------------------------------------------
__global__ __launch_bounds__(256) void z2_mma_kernel(const float* __restrict__ aV)
{
    __shared__ __nv_bfloat16 sAh[128][40];
    __shared__ __nv_bfloat16 sAl[128][40];
    __shared__ __nv_bfloat16 sBh[32][72];
    __shared__ __nv_bfloat16 sBl[32][72];

    int tid = threadIdx.x;
    int lane = tid & 31, wid = tid >> 5;
    int wi = wid >> 1, wd = wid & 1;

    int hm0 = blockIdx.x * 128;
    int i = blockIdx.y;
    const float* Bb = aV + (size_t)i * (L_ * DH_);

    float acc[2][4][4];
    #pragma unroll
    for (int a = 0; a < 2; a++)
        #pragma unroll
        for (int b = 0; b < 4; b++)
            #pragma unroll
            for (int c = 0; c < 4; c++) acc[a][b][c] = 0.f;

    int rowA = wi * 32 + (lane & 15);
    int colA = (lane >> 4) * 8;
    uint32_t aAh = smem_u32(&sAh[rowA][colA]);
    uint32_t aAl = smem_u32(&sAl[rowA][colA]);
    int rowBt = lane & 15;
    int colBt = wd * 32 + ((lane >> 4) << 3);
    uint32_t aBh = smem_u32(&sBh[rowBt][colBt]);
    uint32_t aBl = smem_u32(&sBl[rowBt][colBt]);

    for (int jt = 0; jt < 8; jt++) {
        int k0 = jt * 32;
        #pragma unroll
        for (int it = 0; it < 4; it++) {
            int idx = tid + 256 * it;
            int row = idx >> 3, cg = (idx & 7) * 4;
            float4 va = *(const float4*)(g_S + (size_t)(hm0 + row) * (L_ * L_) + (size_t)i * 256 + k0 + cg);
            cvt_store(va, &sAh[row][cg], &sAl[row][cg]);
        }
        #pragma unroll
        for (int it = 0; it < 2; it++) {
            int idx = tid + 256 * it;
            int jr = idx >> 4, cg = (idx & 15) * 4;
            float4 vb = *(const float4*)(Bb + (size_t)(k0 + jr) * 64 + cg);
            cvt_store(vb, &sBh[jr][cg], &sBl[jr][cg]);
        }
        __syncthreads();

        #pragma unroll
        for (int ks = 0; ks < 2; ks++) {
            uint32_t ah[2][4], al[2][4], bh[4][2], bl[4][2];
            #pragma unroll
            for (int mt = 0; mt < 2; mt++) {
                uint32_t off = (uint32_t)(mt * 16 * 40 + ks * 16) * 2;
                ldm_x4(ah[mt], aAh + off);
                ldm_x4(al[mt], aAl + off);
            }
            #pragma unroll
            for (int nn = 0; nn < 2; nn++) {
                uint32_t off = (uint32_t)(ks * 16 * 72 + nn * 16) * 2;
                uint32_t t[4];
                ldm_x4_trans(t, aBh + off);
                bh[nn * 2][0] = t[0]; bh[nn * 2][1] = t[1];
                bh[nn * 2 + 1][0] = t[2]; bh[nn * 2 + 1][1] = t[3];
                ldm_x4_trans(t, aBl + off);
                bl[nn * 2][0] = t[0]; bl[nn * 2][1] = t[1];
                bl[nn * 2 + 1][0] = t[2]; bl[nn * 2 + 1][1] = t[3];
            }
            #pragma unroll
            for (int mt = 0; mt < 2; mt++) {
                #pragma unroll
                for (int nt = 0; nt < 4; nt++) {
                    mma_bf16(acc[mt][nt], ah[mt], bh[nt]);
                    mma_bf16(acc[mt][nt], ah[mt], bl[nt]);
                    mma_bf16(acc[mt][nt], al[mt], bh[nt]);
                }
            }
        }
        __syncthreads();
    }

    #pragma unroll
    for (int mt = 0; mt < 2; mt++) {
        #pragma unroll
        for (int nt = 0; nt < 4; nt++) {
            int hmr = hm0 + wi * 32 + mt * 16 + (lane >> 2);
            int col = wd * 32 + nt * 8 + (lane & 3) * 2;
            float* p = g_z + (size_t)hmr * (L_ * DH_) + (size_t)i * 64 + col;
            float2 o = *(float2*)p;
            o.x += acc[mt][nt][0]; o.y += acc[mt][nt][1];
            *(float2*)p = o;
            float* p2 = p + (size_t)8 * (L_ * DH_);
            float2 o2 = *(float2*)p2;
            o2.x += acc[mt][nt][2]; o2.y += acc[mt][nt][3];
            *(float2*)p2 = o2;
        }
    }
}

// ---------------------------------------------------------------------------
// Kernel 5: out[i, h*64+d] = sum_m z[(h*64+m), i, d]
// ---------------------------------------------------------------------------
__global__ __launch_bounds__(512) void reduce_kernel(float* __restrict__ out)
{
    int i = blockIdx.x;
    int e = threadIdx.x;
    int h = e >> 6, d = e & 63;
    const float* p = g_z + (h * 64) * (L_ * DH_) + i * DH_ + d;
    float s = 0.f;
    #pragma unroll 8
    for (int m = 0; m < 64; m++) s += p[m * (L_ * DH_)];
    out[i * 512 + e] = s;
}

// ---------------------------------------------------------------------------
extern "C" void kernel_launch(void* const* d_in, const int* in_sizes, int n_in,
                              void* d_out, int out_size)
{
    const float* x  = (const float*)d_in[0];
    const float* Wq = (const float*)d_in[1];
    const float* Wk = (const float*)d_in[2];
    const float* Wv = (const float*)d_in[3];
    const float* aK = (const float*)d_in[4];
    const float* aV = (const float*)d_in[5];
    float* out = (float*)d_out;

    static __nv_bfloat16 *xhi = nullptr, *xlo = nullptr, *whi = nullptr, *wlo = nullptr;
    if (!xhi) {
        cudaGetSymbolAddress((void**)&xhi, g_xhi);
        cudaGetSymbolAddress((void**)&xlo, g_xlo);
        cudaGetSymbolAddress((void**)&whi, g_whi);
        cudaGetSymbolAddress((void**)&wlo, g_wlo);
    }

    split_kernel<<<8192, 256>>>(x, xhi, xlo, 16384 * 512);
    split_kernel<<<256, 256>>>(Wq, whi, wlo, 512 * 512);
    split_kernel<<<256, 256>>>(Wk, whi + 512 * 512, wlo + 512 * 512, 512 * 512);
    split_kernel<<<256, 256>>>(Wv, whi + 2 * 512 * 512, wlo + 2 * 512 * 512, 512 * 512);

    proj_mma_kernel<<<dim3(4, 128, 3), 256>>>();
    e1_mma_kernel  <<<dim3(2, 2, 512), 256>>>();
    e2_mma_kernel  <<<dim3(2, 4, 256), 256>>>(aK);
    softmax_kernel <<<dim3(HM_ * L_ / 8), 256>>>();
    z1_mma_kernel  <<<dim3(2, 512), 256>>>();
    z2_mma_kernel  <<<dim3(4, 256), 256>>>(aV);
    reduce_kernel  <<<dim3(L_), 512>>>(out);
}